// round 1
// baseline (speedup 1.0000x reference)
#include <cuda_runtime.h>
#include <math.h>

#define GEMM_M 512
#define GEMM_N 4096
#define GEMM_K 512
#define NBATCH 16
#define BD_TOTAL (NBATCH * GEMM_M)   // 8192 (B * dim)
#define SCALE 0.04419417382415922f   // 512^-0.5

// Scratch for projected wq / wk / wv: 3 x 16 x 512 x 4096 floats (=1.5 GB, static device mem)
__device__ float g_w[3][(size_t)NBATCH * GEMM_M * GEMM_N];

// ---------------------------------------------------------------------------
// SGEMM: Y[batch][o][l] = sum_c W[o][c] * X[batch][c][l] + bias[o]
// 128x128 block tile, K-tile 8, 256 threads, 8x8 microtile per thread.
// ---------------------------------------------------------------------------
__global__ __launch_bounds__(256) void sgemm_bias(
    const float* __restrict__ W,     // [512,512]
    const float* __restrict__ bias,  // [512]
    const float* __restrict__ X,     // [16,512,4096]
    int which)
{
    float* __restrict__ Yall = g_w[which];

    const int batch = blockIdx.z;
    const float* __restrict__ B = X + (size_t)batch * GEMM_K * GEMM_N;
    float* __restrict__ C = Yall + (size_t)batch * GEMM_M * GEMM_N;

    const int m0 = blockIdx.y * 128;
    const int n0 = blockIdx.x * 128;

    __shared__ float As[8][128];
    __shared__ float Bs[8][128];

    const int tid = threadIdx.x;
    const int arow = tid >> 1;          // 0..127
    const int acol = (tid & 1) * 4;     // 0 or 4
    const int brow = tid >> 5;          // 0..7
    const int bcol = (tid & 31) * 4;    // 0..124
    const int tx = tid & 15;
    const int ty = tid >> 4;

    float acc[8][8];
    #pragma unroll
    for (int i = 0; i < 8; i++)
        #pragma unroll
        for (int j = 0; j < 8; j++) acc[i][j] = 0.0f;

    for (int k0 = 0; k0 < GEMM_K; k0 += 8) {
        float4 a = *(const float4*)&W[(m0 + arow) * GEMM_K + k0 + acol];
        As[acol + 0][arow] = a.x;
        As[acol + 1][arow] = a.y;
        As[acol + 2][arow] = a.z;
        As[acol + 3][arow] = a.w;
        *(float4*)&Bs[brow][bcol] =
            *(const float4*)&B[(size_t)(k0 + brow) * GEMM_N + n0 + bcol];
        __syncthreads();

        #pragma unroll
        for (int k = 0; k < 8; k++) {
            float ra[8], rb[8];
            *(float4*)(ra)     = *(float4*)&As[k][ty * 8];
            *(float4*)(ra + 4) = *(float4*)&As[k][ty * 8 + 4];
            *(float4*)(rb)     = *(float4*)&Bs[k][tx * 8];
            *(float4*)(rb + 4) = *(float4*)&Bs[k][tx * 8 + 4];
            #pragma unroll
            for (int i = 0; i < 8; i++)
                #pragma unroll
                for (int j = 0; j < 8; j++)
                    acc[i][j] = fmaf(ra[i], rb[j], acc[i][j]);
        }
        __syncthreads();
    }

    #pragma unroll
    for (int i = 0; i < 8; i++) {
        const int m = m0 + ty * 8 + i;
        const float bv = bias[m];
        float4 v0, v1;
        v0.x = acc[i][0] + bv; v0.y = acc[i][1] + bv;
        v0.z = acc[i][2] + bv; v0.w = acc[i][3] + bv;
        v1.x = acc[i][4] + bv; v1.y = acc[i][5] + bv;
        v1.z = acc[i][6] + bv; v1.w = acc[i][7] + bv;
        float* cp = &C[(size_t)m * GEMM_N + n0 + tx * 8];
        *(float4*)(cp)     = v0;
        *(float4*)(cp + 4) = v1;
    }
}

// ---------------------------------------------------------------------------
// Attention per (b,d) pair: one block per bd (8192 blocks), 256 threads.
// Qm[p][i] = wq[bd, p*64+i]; Km[p][j] = wk[bd, p*64+j]; Vm[h][j] = wv[bd, h*64+j]
// S[i][j] = scale * sum_p Qm[p][i]*Km[p][j]; attn = softmax_j(S)
// out[bd][o] = bo[o] + sum_h Wo[o][h] * (sum_j attn[0][j] * Vm[h][j]), h<32
// ---------------------------------------------------------------------------
#define QS_STRIDE 68   // padded; also reused for S
#define V_STRIDE  65

__global__ __launch_bounds__(256) void attn_kernel(
    const float* __restrict__ Wo,   // [32,32]
    const float* __restrict__ bo,   // [32]
    float* __restrict__ out_ptr,    // [8192,32] or null
    float* __restrict__ attn_ptr)   // [8192,64,64] or null
{
    const int bd = blockIdx.x;
    const int tid = threadIdx.x;
    const size_t base = (size_t)bd * 4096;

    const float* __restrict__ wq = g_w[0] + base;
    const float* __restrict__ wk = g_w[1] + base;
    const float* __restrict__ wv = g_w[2] + base;

    __shared__ float sQS[64 * QS_STRIDE];  // Q first, then reused for S/attn
    __shared__ float sK[64 * 64];
    __shared__ float sV[32 * V_STRIDE];
    __shared__ float sSlice[32];

    // load tiles (coalesced)
    for (int idx = tid; idx < 4096; idx += 256) {
        sQS[(idx >> 6) * QS_STRIDE + (idx & 63)] = wq[idx];
        sK[idx] = wk[idx];
    }
    for (int idx = tid; idx < 2048; idx += 256)
        sV[(idx >> 6) * V_STRIDE + (idx & 63)] = wv[idx];
    __syncthreads();

    // scores: thread owns column j = tid&63, rows ig*16..ig*16+15
    const int j = tid & 63;
    const int ig = tid >> 6;
    float acc[16];
    #pragma unroll
    for (int ii = 0; ii < 16; ii++) acc[ii] = 0.0f;

    #pragma unroll 4
    for (int p = 0; p < 64; p++) {
        const float kv = sK[p * 64 + j];
        const float* qrow = &sQS[p * QS_STRIDE + ig * 16];
        float4 q0 = *(const float4*)(qrow);
        float4 q1 = *(const float4*)(qrow + 4);
        float4 q2 = *(const float4*)(qrow + 8);
        float4 q3 = *(const float4*)(qrow + 12);
        acc[0]  = fmaf(q0.x, kv, acc[0]);  acc[1]  = fmaf(q0.y, kv, acc[1]);
        acc[2]  = fmaf(q0.z, kv, acc[2]);  acc[3]  = fmaf(q0.w, kv, acc[3]);
        acc[4]  = fmaf(q1.x, kv, acc[4]);  acc[5]  = fmaf(q1.y, kv, acc[5]);
        acc[6]  = fmaf(q1.z, kv, acc[6]);  acc[7]  = fmaf(q1.w, kv, acc[7]);
        acc[8]  = fmaf(q2.x, kv, acc[8]);  acc[9]  = fmaf(q2.y, kv, acc[9]);
        acc[10] = fmaf(q2.z, kv, acc[10]); acc[11] = fmaf(q2.w, kv, acc[11]);
        acc[12] = fmaf(q3.x, kv, acc[12]); acc[13] = fmaf(q3.y, kv, acc[13]);
        acc[14] = fmaf(q3.z, kv, acc[14]); acc[15] = fmaf(q3.w, kv, acc[15]);
    }
    __syncthreads();  // everyone done reading Q before overwrite

    // S overwrites the Q buffer (scaled)
    #pragma unroll
    for (int ii = 0; ii < 16; ii++)
        sQS[(ig * 16 + ii) * QS_STRIDE + j] = acc[ii] * SCALE;
    __syncthreads();

    // row softmax: thread i handles row i (first 64 threads)
    if (tid < 64) {
        float* row = &sQS[tid * QS_STRIDE];
        float m = row[0];
        #pragma unroll 8
        for (int c = 1; c < 64; c++) m = fmaxf(m, row[c]);
        float s = 0.0f;
        #pragma unroll 8
        for (int c = 0; c < 64; c++) {
            float e = __expf(row[c] - m);
            row[c] = e;
            s += e;
        }
        const float inv = 1.0f / s;
        #pragma unroll 8
        for (int c = 0; c < 64; c++) row[c] *= inv;
    }
    __syncthreads();

    // coalesced attn writeback
    if (attn_ptr) {
        float* dst = attn_ptr + base;
        for (int idx = tid; idx < 4096; idx += 256)
            dst[idx] = sQS[(idx >> 6) * QS_STRIDE + (idx & 63)];
    }

    // out epilogue: slice[h] = sum_j attn[0][j] * Vm[h][j]  (h < 32)
    if (out_ptr) {
        if (tid < 32) {
            const int h = tid;
            float s = 0.0f;
            #pragma unroll 8
            for (int c = 0; c < 64; c++)
                s = fmaf(sQS[c], sV[h * V_STRIDE + c], s);
            sSlice[h] = s;
        }
        __syncthreads();
        if (tid < 32) {
            const int o = tid;
            float r = bo[o];
            #pragma unroll 8
            for (int h = 0; h < 32; h++)
                r = fmaf(Wo[o * 32 + h], sSlice[h], r);
            out_ptr[(size_t)bd * 32 + o] = r;
        }
    }
}

// ---------------------------------------------------------------------------
extern "C" void kernel_launch(void* const* d_in, const int* in_sizes, int n_in,
                              void* d_out, int out_size)
{
    const float* Q  = (const float*)d_in[0];
    const float* K  = (const float*)d_in[1];
    const float* V  = (const float*)d_in[2];
    const float* Wq = (const float*)d_in[3];
    const float* bq = (const float*)d_in[4];
    const float* Wk = (const float*)d_in[5];
    const float* bk = (const float*)d_in[6];
    const float* Wv = (const float*)d_in[7];
    const float* bv = (const float*)d_in[8];
    const float* Wo = (const float*)d_in[9];
    const float* bo = (const float*)d_in[10];

    dim3 gg(GEMM_N / 128, GEMM_M / 128, NBATCH);
    sgemm_bias<<<gg, 256>>>(Wq, bq, Q, 0);
    sgemm_bias<<<gg, 256>>>(Wk, bk, K, 1);
    sgemm_bias<<<gg, 256>>>(Wv, bv, V, 2);

    const long long OUTE  = (long long)BD_TOTAL * 32;          // 262144
    const long long ATTNE = (long long)BD_TOTAL * 64 * 64;     // 33554432
    float* out_ptr  = nullptr;
    float* attn_ptr = nullptr;
    if ((long long)out_size == OUTE) {
        out_ptr = (float*)d_out;
    } else if ((long long)out_size == ATTNE) {
        attn_ptr = (float*)d_out;
    } else {  // concatenated [out | attn] (reference returns a tuple)
        out_ptr = (float*)d_out;
        attn_ptr = (float*)d_out + OUTE;
    }

    attn_kernel<<<BD_TOTAL, 256>>>(Wo, bo, out_ptr, attn_ptr);
}

// round 11
// speedup vs baseline: 2.3841x; 2.3841x over previous
#include <cuda_runtime.h>
#include <cuda_bf16.h>
#include <cstdint>
#include <math.h>

#define DIMC 512
#define LLEN 4096
#define NBATCH 16
#define BD_TOTAL (NBATCH * DIMC)         // 8192
#define SCALE 0.04419417382415922f       // 512^-0.5
#define XELEMS ((size_t)NBATCH * DIMC * LLEN)   // 33554432

// fp32 projected outputs (read by attention)
__device__ float g_w[3][XELEMS];
// bf16 hi/lo splits
__device__ __align__(16) __nv_bfloat16 g_xs[3][2][XELEMS];
__device__ __align__(16) __nv_bfloat16 g_ws[3][2][DIMC * DIMC];

// ---------------------------------------------------------------------------
// helpers (sm_80-level features only: cp.async + mma.sync — safe on sm_103)
// ---------------------------------------------------------------------------
__device__ __forceinline__ uint32_t smem_u32(const void* p) {
    uint32_t a;
    asm("{ .reg .u64 t; cvta.to.shared.u64 t, %1; cvt.u32.u64 %0, t; }"
        : "=r"(a) : "l"(p));
    return a;
}
__device__ __forceinline__ void cp16(uint32_t dst, const void* src) {
    asm volatile("cp.async.cg.shared.global [%0], [%1], 16;" :: "r"(dst), "l"(src));
}
#define CP_COMMIT() asm volatile("cp.async.commit_group;" ::: "memory")
#define CP_WAIT0()  asm volatile("cp.async.wait_group 0;" ::: "memory")

__device__ __forceinline__ void mma_bf16(float* c, const uint32_t* a, const uint32_t* b) {
    asm volatile(
        "mma.sync.aligned.m16n8k16.row.col.f32.bf16.bf16.f32 "
        "{%0,%1,%2,%3}, {%4,%5,%6,%7}, {%8,%9}, {%0,%1,%2,%3};"
        : "+f"(c[0]), "+f"(c[1]), "+f"(c[2]), "+f"(c[3])
        : "r"(a[0]), "r"(a[1]), "r"(a[2]), "r"(a[3]), "r"(b[0]), "r"(b[1]));
}

// ---------------------------------------------------------------------------
// Split fp32 -> bf16 hi/lo
// ---------------------------------------------------------------------------
__global__ __launch_bounds__(256) void split_kernel(const float4* __restrict__ in,
                                                    int proj, int is_w, int n4) {
    __nv_bfloat16* hi = is_w ? g_ws[proj][0] : g_xs[proj][0];
    __nv_bfloat16* lo = is_w ? g_ws[proj][1] : g_xs[proj][1];
    uint2* hp = (uint2*)hi;
    uint2* lp = (uint2*)lo;
    int i = blockIdx.x * blockDim.x + threadIdx.x;
    const int stride = gridDim.x * blockDim.x;
    for (; i < n4; i += stride) {
        float4 v = in[i];
        __nv_bfloat16 h0 = __float2bfloat16(v.x);
        __nv_bfloat16 h1 = __float2bfloat16(v.y);
        __nv_bfloat16 h2 = __float2bfloat16(v.z);
        __nv_bfloat16 h3 = __float2bfloat16(v.w);
        __nv_bfloat16 l0 = __float2bfloat16(v.x - __bfloat162float(h0));
        __nv_bfloat16 l1 = __float2bfloat16(v.y - __bfloat162float(h1));
        __nv_bfloat16 l2 = __float2bfloat16(v.z - __bfloat162float(h2));
        __nv_bfloat16 l3 = __float2bfloat16(v.w - __bfloat162float(h3));
        uint2 ph, pl;
        ph.x = (uint32_t)__bfloat16_as_ushort(h0) | ((uint32_t)__bfloat16_as_ushort(h1) << 16);
        ph.y = (uint32_t)__bfloat16_as_ushort(h2) | ((uint32_t)__bfloat16_as_ushort(h3) << 16);
        pl.x = (uint32_t)__bfloat16_as_ushort(l0) | ((uint32_t)__bfloat16_as_ushort(l1) << 16);
        pl.y = (uint32_t)__bfloat16_as_ushort(l2) | ((uint32_t)__bfloat16_as_ushort(l3) << 16);
        hp[i] = ph;
        lp[i] = pl;
    }
}

// ---------------------------------------------------------------------------
// mma.sync GEMM: Y[bz][m][n] = sum_k W[m][k]*X[k][n] + bias[m]  (fp32 out)
// CTA 128x128, 8 warps (2m x 4n), warp tile 64x32, K-tile 32, double buffer.
// bf16 2-term split: acc += Wh*Xh + Wh*Xl + Wl*Xh.
// V projection (proj==2) only needs n < 2048 -> skip nb >= 16.
// ---------------------------------------------------------------------------
#define SA 40      // A smem row stride (bf16 elems), 80B rows (16B-aligned)
#define SX 136     // X smem row stride (bf16 elems), 272B rows (16B-aligned)
#define A_BYTES (128 * SA * 2)              // 10240
#define X_BYTES (32 * SX * 2)               // 8704
#define BUF_BYTES (2 * A_BYTES + 2 * X_BYTES)  // 37888
#define SM_TOTAL (2 * BUF_BYTES)               // 75776

__global__ __launch_bounds__(256) void gemm_mma(const float* __restrict__ bq,
                                                const float* __restrict__ bk,
                                                const float* __restrict__ bv) {
    const int bz = blockIdx.z;
    const int proj = bz >> 4, batch = bz & 15;
    const int nb = blockIdx.x, mb = blockIdx.y;
    if (proj == 2 && nb >= 16) return;   // V output slice only needs l < 2048
    const int m0 = mb * 128, n0 = nb * 128;

    extern __shared__ __align__(16) unsigned char sm[];
    const uint32_t sb = smem_u32(sm);
    const int tid = threadIdx.x, wid = tid >> 5, lane = tid & 31;
    const int lr = lane >> 2, lc = lane & 3;
    const int wm = (wid & 1) * 64, wn = (wid >> 1) * 32;

    const __nv_bfloat16* __restrict__ Whi = g_ws[proj][0];
    const __nv_bfloat16* __restrict__ Wlo = g_ws[proj][1];
    const __nv_bfloat16* __restrict__ Xhi = g_xs[proj][0] + (size_t)batch * DIMC * LLEN;
    const __nv_bfloat16* __restrict__ Xlo = g_xs[proj][1] + (size_t)batch * DIMC * LLEN;

    float acc[4][4][4];
    #pragma unroll
    for (int i = 0; i < 4; i++)
        #pragma unroll
        for (int j = 0; j < 4; j++)
            #pragma unroll
            for (int q = 0; q < 4; q++) acc[i][j][q] = 0.0f;

    // issue all cp.async for one buffer (A: W hi/lo 128x32; X: hi/lo 32x128)
    auto ldbuf = [&](int buf, int k0) {
        const uint32_t aBase = sb + buf * BUF_BYTES;
        #pragma unroll
        for (int p = 0; p < 4; p++) {                 // 2 mats * 128 rows * 4 ch
            int id = p * 256 + tid;
            int mat = id >> 9, row = (id >> 2) & 127, ch = id & 3;
            const __nv_bfloat16* src =
                (mat ? Wlo : Whi) + (size_t)(m0 + row) * DIMC + k0 + ch * 8;
            cp16(aBase + mat * A_BYTES + (row * SA + ch * 8) * 2, src);
        }
        const uint32_t xBase = sb + buf * BUF_BYTES + 2 * A_BYTES;
        #pragma unroll
        for (int p = 0; p < 4; p++) {                 // 2 mats * 32 rows * 16 ch
            int id = p * 256 + tid;
            int mat = id >> 9, row = (id >> 4) & 31, ch = id & 15;
            const __nv_bfloat16* src =
                (mat ? Xlo : Xhi) + (size_t)(k0 + row) * LLEN + n0 + ch * 8;
            cp16(xBase + mat * X_BYTES + (row * SX + ch * 8) * 2, src);
        }
    };

    ldbuf(0, 0);
    CP_COMMIT();

    for (int c = 0; c < 16; c++) {
        CP_WAIT0();
        __syncthreads();                 // cur buffer ready; prev compute finished
        if (c < 15) {                    // prefetch next while computing cur
            ldbuf((c + 1) & 1, (c + 1) * 32);
            CP_COMMIT();
        }

        const unsigned char* AH = sm + (c & 1) * BUF_BYTES;
        const unsigned char* AL = AH + A_BYTES;
        const unsigned short* xh = (const unsigned short*)(AH + 2 * A_BYTES);
        const unsigned short* xl = (const unsigned short*)(AH + 2 * A_BYTES + X_BYTES);

        #pragma unroll
        for (int ks = 0; ks < 2; ks++) {
            uint32_t ah[4][4], al[4][4], bh[4][2], bl[4][2];
            #pragma unroll
            for (int mt = 0; mt < 4; mt++) {
                int r = wm + mt * 16 + lr;
                int off = (r * SA + ks * 16 + 2 * lc) * 2;
                ah[mt][0] = *(const uint32_t*)(AH + off);
                ah[mt][1] = *(const uint32_t*)(AH + off + 8 * SA * 2);
                ah[mt][2] = *(const uint32_t*)(AH + off + 16);
                ah[mt][3] = *(const uint32_t*)(AH + off + 8 * SA * 2 + 16);
                al[mt][0] = *(const uint32_t*)(AL + off);
                al[mt][1] = *(const uint32_t*)(AL + off + 8 * SA * 2);
                al[mt][2] = *(const uint32_t*)(AL + off + 16);
                al[mt][3] = *(const uint32_t*)(AL + off + 8 * SA * 2 + 16);
            }
            #pragma unroll
            for (int nt = 0; nt < 4; nt++) {
                int n = wn + nt * 8 + lr;
                int k = ks * 16 + 2 * lc;
                bh[nt][0] = (uint32_t)xh[k * SX + n] | ((uint32_t)xh[(k + 1) * SX + n] << 16);
                bh[nt][1] = (uint32_t)xh[(k + 8) * SX + n] | ((uint32_t)xh[(k + 9) * SX + n] << 16);
                bl[nt][0] = (uint32_t)xl[k * SX + n] | ((uint32_t)xl[(k + 1) * SX + n] << 16);
                bl[nt][1] = (uint32_t)xl[(k + 8) * SX + n] | ((uint32_t)xl[(k + 9) * SX + n] << 16);
            }
            #pragma unroll
            for (int mt = 0; mt < 4; mt++)
                #pragma unroll
                for (int nt = 0; nt < 4; nt++) {
                    mma_bf16(acc[mt][nt], ah[mt], bh[nt]);
                    mma_bf16(acc[mt][nt], ah[mt], bl[nt]);
                    mma_bf16(acc[mt][nt], al[mt], bh[nt]);
                }
        }
    }

    // epilogue: bias + fp32 store
    const float* bias = (proj == 0) ? bq : (proj == 1) ? bk : bv;
    float* __restrict__ C = g_w[proj] + (size_t)batch * DIMC * LLEN;
    #pragma unroll
    for (int mt = 0; mt < 4; mt++) {
        int r0 = m0 + wm + mt * 16 + lr;
        float bv0 = bias[r0], bv1 = bias[r0 + 8];
        #pragma unroll
        for (int nt = 0; nt < 4; nt++) {
            int n = n0 + wn + nt * 8 + 2 * lc;
            float2 v0, v1;
            v0.x = acc[mt][nt][0] + bv0; v0.y = acc[mt][nt][1] + bv0;
            v1.x = acc[mt][nt][2] + bv1; v1.y = acc[mt][nt][3] + bv1;
            *(float2*)(C + (size_t)r0 * LLEN + n) = v0;
            *(float2*)(C + (size_t)(r0 + 8) * LLEN + n) = v1;
        }
    }
}

// ---------------------------------------------------------------------------
// Attention per (b,d) pair (unchanged from passing R1 kernel)
// ---------------------------------------------------------------------------
#define QS_STRIDE 68
#define V_STRIDE  65

__global__ __launch_bounds__(256) void attn_kernel(
    const float* __restrict__ Wo, const float* __restrict__ bo,
    float* __restrict__ out_ptr, float* __restrict__ attn_ptr) {
    const int bd = blockIdx.x;
    const int tid = threadIdx.x;
    const size_t base = (size_t)bd * 4096;

    const float* __restrict__ wq = g_w[0] + base;
    const float* __restrict__ wk = g_w[1] + base;
    const float* __restrict__ wv = g_w[2] + base;

    __shared__ float sQS[64 * QS_STRIDE];
    __shared__ float sK[64 * 64];
    __shared__ float sV[32 * V_STRIDE];
    __shared__ float sSlice[32];

    for (int idx = tid; idx < 4096; idx += 256) {
        sQS[(idx >> 6) * QS_STRIDE + (idx & 63)] = wq[idx];
        sK[idx] = wk[idx];
    }
    for (int idx = tid; idx < 2048; idx += 256)
        sV[(idx >> 6) * V_STRIDE + (idx & 63)] = wv[idx];
    __syncthreads();

    const int j = tid & 63;
    const int ig = tid >> 6;
    float acc[16];
    #pragma unroll
    for (int ii = 0; ii < 16; ii++) acc[ii] = 0.0f;

    #pragma unroll 4
    for (int p = 0; p < 64; p++) {
        const float kv = sK[p * 64 + j];
        const float* qrow = &sQS[p * QS_STRIDE + ig * 16];
        float4 q0 = *(const float4*)(qrow);
        float4 q1 = *(const float4*)(qrow + 4);
        float4 q2 = *(const float4*)(qrow + 8);
        float4 q3 = *(const float4*)(qrow + 12);
        acc[0]  = fmaf(q0.x, kv, acc[0]);  acc[1]  = fmaf(q0.y, kv, acc[1]);
        acc[2]  = fmaf(q0.z, kv, acc[2]);  acc[3]  = fmaf(q0.w, kv, acc[3]);
        acc[4]  = fmaf(q1.x, kv, acc[4]);  acc[5]  = fmaf(q1.y, kv, acc[5]);
        acc[6]  = fmaf(q1.z, kv, acc[6]);  acc[7]  = fmaf(q1.w, kv, acc[7]);
        acc[8]  = fmaf(q2.x, kv, acc[8]);  acc[9]  = fmaf(q2.y, kv, acc[9]);
        acc[10] = fmaf(q2.z, kv, acc[10]); acc[11] = fmaf(q2.w, kv, acc[11]);
        acc[12] = fmaf(q3.x, kv, acc[12]); acc[13] = fmaf(q3.y, kv, acc[13]);
        acc[14] = fmaf(q3.z, kv, acc[14]); acc[15] = fmaf(q3.w, kv, acc[15]);
    }
    __syncthreads();

    #pragma unroll
    for (int ii = 0; ii < 16; ii++)
        sQS[(ig * 16 + ii) * QS_STRIDE + j] = acc[ii] * SCALE;
    __syncthreads();

    if (tid < 64) {
        float* row = &sQS[tid * QS_STRIDE];
        float m = row[0];
        #pragma unroll 8
        for (int c = 1; c < 64; c++) m = fmaxf(m, row[c]);
        float s = 0.0f;
        #pragma unroll 8
        for (int c = 0; c < 64; c++) {
            float e = __expf(row[c] - m);
            row[c] = e;
            s += e;
        }
        const float inv = 1.0f / s;
        #pragma unroll 8
        for (int c = 0; c < 64; c++) row[c] *= inv;
    }
    __syncthreads();

    if (attn_ptr) {
        float* dst = attn_ptr + base;
        for (int idx = tid; idx < 4096; idx += 256)
            dst[idx] = sQS[(idx >> 6) * QS_STRIDE + (idx & 63)];
    }

    if (out_ptr) {
        if (tid < 32) {
            const int h = tid;
            float s = 0.0f;
            #pragma unroll 8
            for (int c = 0; c < 64; c++)
                s = fmaf(sQS[c], sV[h * V_STRIDE + c], s);
            sSlice[h] = s;
        }
        __syncthreads();
        if (tid < 32) {
            const int o = tid;
            float r = bo[o];
            #pragma unroll 8
            for (int h = 0; h < 32; h++)
                r = fmaf(Wo[o * 32 + h], sSlice[h], r);
            out_ptr[(size_t)bd * 32 + o] = r;
        }
    }
}

// ---------------------------------------------------------------------------
extern "C" void kernel_launch(void* const* d_in, const int* in_sizes, int n_in,
                              void* d_out, int out_size)
{
    const float* Q  = (const float*)d_in[0];
    const float* K  = (const float*)d_in[1];
    const float* V  = (const float*)d_in[2];
    const float* Wq = (const float*)d_in[3];
    const float* bq = (const float*)d_in[4];
    const float* Wk = (const float*)d_in[5];
    const float* bk = (const float*)d_in[6];
    const float* Wv = (const float*)d_in[7];
    const float* bv = (const float*)d_in[8];
    const float* Wo = (const float*)d_in[9];
    const float* bo = (const float*)d_in[10];

    // split fp32 -> bf16 hi/lo
    const int xn4 = (int)(XELEMS / 4);
    const int wn4 = DIMC * DIMC / 4;
    split_kernel<<<8192, 256>>>((const float4*)Q,  0, 0, xn4);
    split_kernel<<<8192, 256>>>((const float4*)K,  1, 0, xn4);
    split_kernel<<<8192, 256>>>((const float4*)V,  2, 0, xn4);
    split_kernel<<<256, 256>>>((const float4*)Wq, 0, 1, wn4);
    split_kernel<<<256, 256>>>((const float4*)Wk, 1, 1, wn4);
    split_kernel<<<256, 256>>>((const float4*)Wv, 2, 1, wn4);

    // tensor-core (HMMA) projections
    static int smem_set = 0;
    if (!smem_set) {
        cudaFuncSetAttribute(gemm_mma, cudaFuncAttributeMaxDynamicSharedMemorySize, SM_TOTAL);
        smem_set = 1;
    }
    dim3 gg(LLEN / 128, DIMC / 128, 3 * NBATCH);
    gemm_mma<<<gg, 256, SM_TOTAL>>>(bq, bk, bv);

    // attention + epilogue
    const long long OUTE  = (long long)BD_TOTAL * 32;
    const long long ATTNE = (long long)BD_TOTAL * 64 * 64;
    float* out_ptr  = nullptr;
    float* attn_ptr = nullptr;
    if ((long long)out_size == OUTE) {
        out_ptr = (float*)d_out;
    } else if ((long long)out_size == ATTNE) {
        attn_ptr = (float*)d_out;
    } else {
        out_ptr = (float*)d_out;
        attn_ptr = (float*)d_out + OUTE;
    }
    attn_kernel<<<BD_TOTAL, 256>>>(Wo, bo, out_ptr, attn_ptr);
}

// round 12
// speedup vs baseline: 2.5831x; 1.0835x over previous
#include <cuda_runtime.h>
#include <cuda_bf16.h>
#include <cstdint>
#include <math.h>

#define DIMC 512
#define LLEN 4096
#define NBATCH 16
#define BD_TOTAL (NBATCH * DIMC)         // 8192
#define SCALE 0.04419417382415922f       // 512^-0.5
#define XELEMS ((size_t)NBATCH * DIMC * LLEN)   // 33554432

// fp32 projected outputs (read by attention)
__device__ float g_w[3][XELEMS];
// bf16 hi/lo splits
__device__ __align__(16) __nv_bfloat16 g_xs[3][2][XELEMS];
__device__ __align__(16) __nv_bfloat16 g_ws[3][2][DIMC * DIMC];

// ---------------------------------------------------------------------------
// helpers (sm_75/80-level features only — safe on plain sm_103 target)
// ---------------------------------------------------------------------------
__device__ __forceinline__ uint32_t smem_u32(const void* p) {
    uint32_t a;
    asm("{ .reg .u64 t; cvta.to.shared.u64 t, %1; cvt.u32.u64 %0, t; }"
        : "=r"(a) : "l"(p));
    return a;
}
__device__ __forceinline__ void cp16(uint32_t dst, const void* src) {
    asm volatile("cp.async.cg.shared.global [%0], [%1], 16;" :: "r"(dst), "l"(src));
}
#define CP_COMMIT() asm volatile("cp.async.commit_group;" ::: "memory")
#define CP_WAIT0()  asm volatile("cp.async.wait_group 0;" ::: "memory")

__device__ __forceinline__ void mma_bf16(float* c, const uint32_t* a, const uint32_t* b) {
    asm volatile(
        "mma.sync.aligned.m16n8k16.row.col.f32.bf16.bf16.f32 "
        "{%0,%1,%2,%3}, {%4,%5,%6,%7}, {%8,%9}, {%0,%1,%2,%3};"
        : "+f"(c[0]), "+f"(c[1]), "+f"(c[2]), "+f"(c[3])
        : "r"(a[0]), "r"(a[1]), "r"(a[2]), "r"(a[3]), "r"(b[0]), "r"(b[1]));
}
__device__ __forceinline__ void ldsm_x4(uint32_t* r, uint32_t addr) {
    asm volatile("ldmatrix.sync.aligned.m8n8.x4.shared.b16 {%0,%1,%2,%3}, [%4];"
        : "=r"(r[0]), "=r"(r[1]), "=r"(r[2]), "=r"(r[3]) : "r"(addr));
}
__device__ __forceinline__ void ldsm_x2t(uint32_t* r, uint32_t addr) {
    asm volatile("ldmatrix.sync.aligned.m8n8.x2.trans.shared.b16 {%0,%1}, [%2];"
        : "=r"(r[0]), "=r"(r[1]) : "r"(addr));
}

// ---------------------------------------------------------------------------
// Merged split: fp32 -> bf16 hi/lo for all 6 tensors in one launch
// blockIdx.y: 0..2 = X proj (Q,K,V), 3..5 = W proj
// ---------------------------------------------------------------------------
__global__ __launch_bounds__(256) void split_all(
    const float4* __restrict__ Q, const float4* __restrict__ K,
    const float4* __restrict__ V, const float4* __restrict__ Wq,
    const float4* __restrict__ Wk, const float4* __restrict__ Wv)
{
    const int which = blockIdx.y;
    const int proj = which % 3;
    const int is_w = which / 3;
    const float4* in = is_w ? (proj == 0 ? Wq : proj == 1 ? Wk : Wv)
                            : (proj == 0 ? Q  : proj == 1 ? K  : V);
    const int n4 = is_w ? (DIMC * DIMC / 4) : (int)(XELEMS / 4);
    uint2* hp = (uint2*)(is_w ? g_ws[proj][0] : g_xs[proj][0]);
    uint2* lp = (uint2*)(is_w ? g_ws[proj][1] : g_xs[proj][1]);

    int i = blockIdx.x * blockDim.x + threadIdx.x;
    const int stride = gridDim.x * blockDim.x;
    for (; i < n4; i += stride) {
        float4 v = in[i];
        __nv_bfloat16 h0 = __float2bfloat16(v.x);
        __nv_bfloat16 h1 = __float2bfloat16(v.y);
        __nv_bfloat16 h2 = __float2bfloat16(v.z);
        __nv_bfloat16 h3 = __float2bfloat16(v.w);
        __nv_bfloat16 l0 = __float2bfloat16(v.x - __bfloat162float(h0));
        __nv_bfloat16 l1 = __float2bfloat16(v.y - __bfloat162float(h1));
        __nv_bfloat16 l2 = __float2bfloat16(v.z - __bfloat162float(h2));
        __nv_bfloat16 l3 = __float2bfloat16(v.w - __bfloat162float(h3));
        uint2 ph, pl;
        ph.x = (uint32_t)__bfloat16_as_ushort(h0) | ((uint32_t)__bfloat16_as_ushort(h1) << 16);
        ph.y = (uint32_t)__bfloat16_as_ushort(h2) | ((uint32_t)__bfloat16_as_ushort(h3) << 16);
        pl.x = (uint32_t)__bfloat16_as_ushort(l0) | ((uint32_t)__bfloat16_as_ushort(l1) << 16);
        pl.y = (uint32_t)__bfloat16_as_ushort(l2) | ((uint32_t)__bfloat16_as_ushort(l3) << 16);
        hp[i] = ph;
        lp[i] = pl;
    }
}

// ---------------------------------------------------------------------------
// mma.sync GEMM with ldmatrix fragment loads.
// CTA 128x128, 8 warps (2m x 4n), warp tile 64x32, K-tile 32, double buffer.
// bf16 2-term split: acc += Wh*Xh + Wh*Xl + Wl*Xh.
// V projection (proj==2) only needs n < 2048 -> skip nb >= 16.
// ---------------------------------------------------------------------------
#define SA 40      // A smem row stride (bf16), 80B rows
#define SX 136     // X smem row stride (bf16), 272B rows
#define A_BYTES (128 * SA * 2)              // 10240
#define X_BYTES (32 * SX * 2)               // 8704
#define BUF_BYTES (2 * A_BYTES + 2 * X_BYTES)  // 37888
#define SM_TOTAL (2 * BUF_BYTES)               // 75776

__global__ __launch_bounds__(256) void gemm_mma(const float* __restrict__ bq,
                                                const float* __restrict__ bk,
                                                const float* __restrict__ bv) {
    const int bz = blockIdx.z;
    const int proj = bz >> 4, batch = bz & 15;
    const int nb = blockIdx.x, mb = blockIdx.y;
    if (proj == 2 && nb >= 16) return;   // V output slice only needs l < 2048
    const int m0 = mb * 128, n0 = nb * 128;

    extern __shared__ __align__(16) unsigned char sm[];
    const uint32_t sb = smem_u32(sm);
    const int tid = threadIdx.x, wid = tid >> 5, lane = tid & 31;
    const int lr = lane >> 2, lc = lane & 3;
    const int wm = (wid & 1) * 64, wn = (wid >> 1) * 32;

    const __nv_bfloat16* __restrict__ Whi = g_ws[proj][0];
    const __nv_bfloat16* __restrict__ Wlo = g_ws[proj][1];
    const __nv_bfloat16* __restrict__ Xhi = g_xs[proj][0] + (size_t)batch * DIMC * LLEN;
    const __nv_bfloat16* __restrict__ Xlo = g_xs[proj][1] + (size_t)batch * DIMC * LLEN;

    float acc[4][4][4];
    #pragma unroll
    for (int i = 0; i < 4; i++)
        #pragma unroll
        for (int j = 0; j < 4; j++)
            #pragma unroll
            for (int q = 0; q < 4; q++) acc[i][j][q] = 0.0f;

    // ldmatrix per-lane base offsets (relative to buffer base)
    // A x4: lanes 0-15 -> rows 0-15, lanes 16-31 -> same rows, k+8
    const uint32_t aOfs = (uint32_t)(((wm + (lane & 15)) * SA + (lane >> 4) * 8) * 2);
    // B x2.trans: lanes 0-15 -> k-rows 0-15 of the tile
    const uint32_t bOfs = (uint32_t)(2 * A_BYTES + (((lane & 15) * SX + wn) * 2));

    auto ldbuf = [&](int buf, int k0) {
        const uint32_t aBase = sb + buf * BUF_BYTES;
        #pragma unroll
        for (int p = 0; p < 4; p++) {                 // 2 mats * 128 rows * 4 ch
            int id = p * 256 + tid;
            int mat = id >> 9, row = (id >> 2) & 127, ch = id & 3;
            const __nv_bfloat16* src =
                (mat ? Wlo : Whi) + (size_t)(m0 + row) * DIMC + k0 + ch * 8;
            cp16(aBase + mat * A_BYTES + (row * SA + ch * 8) * 2, src);
        }
        const uint32_t xBase = sb + buf * BUF_BYTES + 2 * A_BYTES;
        #pragma unroll
        for (int p = 0; p < 4; p++) {                 // 2 mats * 32 rows * 16 ch
            int id = p * 256 + tid;
            int mat = id >> 9, row = (id >> 4) & 31, ch = id & 15;
            const __nv_bfloat16* src =
                (mat ? Xlo : Xhi) + (size_t)(k0 + row) * LLEN + n0 + ch * 8;
            cp16(xBase + mat * X_BYTES + (row * SX + ch * 8) * 2, src);
        }
    };

    ldbuf(0, 0);
    CP_COMMIT();

    for (int c = 0; c < 16; c++) {
        CP_WAIT0();
        __syncthreads();                 // cur buffer ready; prev compute finished
        if (c < 15) {                    // prefetch next while computing cur
            ldbuf((c + 1) & 1, (c + 1) * 32);
            CP_COMMIT();
        }

        const uint32_t base = sb + (c & 1) * BUF_BYTES;
        const uint32_t aHi = base + aOfs;
        const uint32_t bHi = base + bOfs;

        #pragma unroll
        for (int ks = 0; ks < 2; ks++) {
            uint32_t ah[4][4], al[4][4], bh[4][2], bl[4][2];
            #pragma unroll
            for (int mt = 0; mt < 4; mt++) {
                const uint32_t a = aHi + mt * (16 * SA * 2) + ks * 32;
                ldsm_x4(ah[mt], a);
                ldsm_x4(al[mt], a + A_BYTES);
            }
            #pragma unroll
            for (int nt = 0; nt < 4; nt++) {
                const uint32_t b = bHi + nt * 16 + ks * (16 * SX * 2);
                ldsm_x2t(bh[nt], b);
                ldsm_x2t(bl[nt], b + X_BYTES);
            }
            #pragma unroll
            for (int mt = 0; mt < 4; mt++)
                #pragma unroll
                for (int nt = 0; nt < 4; nt++) {
                    mma_bf16(acc[mt][nt], ah[mt], bh[nt]);
                    mma_bf16(acc[mt][nt], ah[mt], bl[nt]);
                    mma_bf16(acc[mt][nt], al[mt], bh[nt]);
                }
        }
    }

    // epilogue: bias + fp32 store
    const float* bias = (proj == 0) ? bq : (proj == 1) ? bk : bv;
    float* __restrict__ C = g_w[proj] + (size_t)batch * DIMC * LLEN;
    #pragma unroll
    for (int mt = 0; mt < 4; mt++) {
        int r0 = m0 + wm + mt * 16 + lr;
        float bv0 = bias[r0], bv1 = bias[r0 + 8];
        #pragma unroll
        for (int nt = 0; nt < 4; nt++) {
            int n = n0 + wn + nt * 8 + 2 * lc;
            float2 v0, v1;
            v0.x = acc[mt][nt][0] + bv0; v0.y = acc[mt][nt][1] + bv0;
            v1.x = acc[mt][nt][2] + bv1; v1.y = acc[mt][nt][3] + bv1;
            *(float2*)(C + (size_t)r0 * LLEN + n) = v0;
            *(float2*)(C + (size_t)(r0 + 8) * LLEN + n) = v1;
        }
    }
}

// ---------------------------------------------------------------------------
// Attention per (b,d): softmax now uses all 256 threads (4 per row)
// ---------------------------------------------------------------------------
#define QS_STRIDE 68
#define V_STRIDE  65

__global__ __launch_bounds__(256) void attn_kernel(
    const float* __restrict__ Wo, const float* __restrict__ bo,
    float* __restrict__ out_ptr, float* __restrict__ attn_ptr) {
    const int bd = blockIdx.x;
    const int tid = threadIdx.x;
    const size_t base = (size_t)bd * 4096;

    const float* __restrict__ wq = g_w[0] + base;
    const float* __restrict__ wk = g_w[1] + base;
    const float* __restrict__ wv = g_w[2] + base;

    __shared__ float sQS[64 * QS_STRIDE];
    __shared__ float sK[64 * 64];
    __shared__ float sV[32 * V_STRIDE];
    __shared__ float sSlice[32];

    for (int idx = tid; idx < 4096; idx += 256) {
        sQS[(idx >> 6) * QS_STRIDE + (idx & 63)] = wq[idx];
        sK[idx] = wk[idx];
    }
    for (int idx = tid; idx < 2048; idx += 256)
        sV[(idx >> 6) * V_STRIDE + (idx & 63)] = wv[idx];
    __syncthreads();

    const int j = tid & 63;
    const int ig = tid >> 6;
    float acc[16];
    #pragma unroll
    for (int ii = 0; ii < 16; ii++) acc[ii] = 0.0f;

    #pragma unroll 4
    for (int p = 0; p < 64; p++) {
        const float kv = sK[p * 64 + j];
        const float* qrow = &sQS[p * QS_STRIDE + ig * 16];
        float4 q0 = *(const float4*)(qrow);
        float4 q1 = *(const float4*)(qrow + 4);
        float4 q2 = *(const float4*)(qrow + 8);
        float4 q3 = *(const float4*)(qrow + 12);
        acc[0]  = fmaf(q0.x, kv, acc[0]);  acc[1]  = fmaf(q0.y, kv, acc[1]);
        acc[2]  = fmaf(q0.z, kv, acc[2]);  acc[3]  = fmaf(q0.w, kv, acc[3]);
        acc[4]  = fmaf(q1.x, kv, acc[4]);  acc[5]  = fmaf(q1.y, kv, acc[5]);
        acc[6]  = fmaf(q1.z, kv, acc[6]);  acc[7]  = fmaf(q1.w, kv, acc[7]);
        acc[8]  = fmaf(q2.x, kv, acc[8]);  acc[9]  = fmaf(q2.y, kv, acc[9]);
        acc[10] = fmaf(q2.z, kv, acc[10]); acc[11] = fmaf(q2.w, kv, acc[11]);
        acc[12] = fmaf(q3.x, kv, acc[12]); acc[13] = fmaf(q3.y, kv, acc[13]);
        acc[14] = fmaf(q3.z, kv, acc[14]); acc[15] = fmaf(q3.w, kv, acc[15]);
    }
    __syncthreads();

    #pragma unroll
    for (int ii = 0; ii < 16; ii++)
        sQS[(ig * 16 + ii) * QS_STRIDE + j] = acc[ii] * SCALE;
    __syncthreads();

    // softmax: 4 threads per row (thread t: row t>>2, cols (t&3)*16 .. +15)
    {
        float* rp = &sQS[(tid >> 2) * QS_STRIDE + (tid & 3) * 16];
        float4 r0 = *(float4*)(rp);
        float4 r1 = *(float4*)(rp + 4);
        float4 r2 = *(float4*)(rp + 8);
        float4 r3 = *(float4*)(rp + 12);
        float m = fmaxf(fmaxf(fmaxf(r0.x, r0.y), fmaxf(r0.z, r0.w)),
                        fmaxf(fmaxf(r1.x, r1.y), fmaxf(r1.z, r1.w)));
        m = fmaxf(m, fmaxf(fmaxf(fmaxf(r2.x, r2.y), fmaxf(r2.z, r2.w)),
                           fmaxf(fmaxf(r3.x, r3.y), fmaxf(r3.z, r3.w))));
        m = fmaxf(m, __shfl_xor_sync(0xffffffffu, m, 1));
        m = fmaxf(m, __shfl_xor_sync(0xffffffffu, m, 2));
        r0.x = __expf(r0.x - m); r0.y = __expf(r0.y - m);
        r0.z = __expf(r0.z - m); r0.w = __expf(r0.w - m);
        r1.x = __expf(r1.x - m); r1.y = __expf(r1.y - m);
        r1.z = __expf(r1.z - m); r1.w = __expf(r1.w - m);
        r2.x = __expf(r2.x - m); r2.y = __expf(r2.y - m);
        r2.z = __expf(r2.z - m); r2.w = __expf(r2.w - m);
        r3.x = __expf(r3.x - m); r3.y = __expf(r3.y - m);
        r3.z = __expf(r3.z - m); r3.w = __expf(r3.w - m);
        float s = (r0.x + r0.y + r0.z + r0.w) + (r1.x + r1.y + r1.z + r1.w)
                + (r2.x + r2.y + r2.z + r2.w) + (r3.x + r3.y + r3.z + r3.w);
        s += __shfl_xor_sync(0xffffffffu, s, 1);
        s += __shfl_xor_sync(0xffffffffu, s, 2);
        const float inv = 1.0f / s;
        r0.x *= inv; r0.y *= inv; r0.z *= inv; r0.w *= inv;
        r1.x *= inv; r1.y *= inv; r1.z *= inv; r1.w *= inv;
        r2.x *= inv; r2.y *= inv; r2.z *= inv; r2.w *= inv;
        r3.x *= inv; r3.y *= inv; r3.z *= inv; r3.w *= inv;
        *(float4*)(rp)      = r0;
        *(float4*)(rp + 4)  = r1;
        *(float4*)(rp + 8)  = r2;
        *(float4*)(rp + 12) = r3;
    }
    __syncthreads();

    if (attn_ptr) {
        float* dst = attn_ptr + base;
        for (int idx = tid; idx < 4096; idx += 256)
            dst[idx] = sQS[(idx >> 6) * QS_STRIDE + (idx & 63)];
    }

    if (out_ptr) {
        if (tid < 32) {
            const int h = tid;
            float s = 0.0f;
            #pragma unroll 8
            for (int c = 0; c < 64; c++)
                s = fmaf(sQS[c], sV[h * V_STRIDE + c], s);
            sSlice[h] = s;
        }
        __syncthreads();
        if (tid < 32) {
            const int o = tid;
            float r = bo[o];
            #pragma unroll 8
            for (int h = 0; h < 32; h++)
                r = fmaf(Wo[o * 32 + h], sSlice[h], r);
            out_ptr[(size_t)bd * 32 + o] = r;
        }
    }
}

// ---------------------------------------------------------------------------
extern "C" void kernel_launch(void* const* d_in, const int* in_sizes, int n_in,
                              void* d_out, int out_size)
{
    const float* Q  = (const float*)d_in[0];
    const float* K  = (const float*)d_in[1];
    const float* V  = (const float*)d_in[2];
    const float* Wq = (const float*)d_in[3];
    const float* bq = (const float*)d_in[4];
    const float* Wk = (const float*)d_in[5];
    const float* bk = (const float*)d_in[6];
    const float* Wv = (const float*)d_in[7];
    const float* bv = (const float*)d_in[8];
    const float* Wo = (const float*)d_in[9];
    const float* bo = (const float*)d_in[10];

    // fused split: all 6 tensors, one launch
    dim3 sg(4096, 6);
    split_all<<<sg, 256>>>((const float4*)Q, (const float4*)K, (const float4*)V,
                           (const float4*)Wq, (const float4*)Wk, (const float4*)Wv);

    // tensor-core (HMMA) projections
    cudaFuncSetAttribute(gemm_mma, cudaFuncAttributeMaxDynamicSharedMemorySize, SM_TOTAL);
    dim3 gg(LLEN / 128, DIMC / 128, 3 * NBATCH);
    gemm_mma<<<gg, 256, SM_TOTAL>>>(bq, bk, bv);

    // attention + epilogue
    const long long OUTE  = (long long)BD_TOTAL * 32;
    const long long ATTNE = (long long)BD_TOTAL * 64 * 64;
    float* out_ptr  = nullptr;
    float* attn_ptr = nullptr;
    if ((long long)out_size == OUTE) {
        out_ptr = (float*)d_out;
    } else if ((long long)out_size == ATTNE) {
        attn_ptr = (float*)d_out;
    } else {
        out_ptr = (float*)d_out;
        attn_ptr = (float*)d_out + OUTE;
    }
    attn_kernel<<<BD_TOTAL, 256>>>(Wo, bo, out_ptr, attn_ptr);
}